// round 12
// baseline (speedup 1.0000x reference)
#include <cuda_runtime.h>
#include <cuda_bf16.h>
#include <stdint.h>

#define BB 4
#define CC 64
#define WDIM 64
#define NN 4096
#define MQ 64
#define KTILE 32
#define NSPLIT 2
#define TILES_PER_SPLIT (NN/KTILE/NSPLIT)   // 64
#define L2E 1.44269504088896f
#define PBLK 64

#define QSTRIDE 80
#define KSTRIDE 80
#define VTSTRIDE 144           // 32 keys * 4B + 16B pad
#define SM_Q   0               // 64 x 80           = 5120
#define SM_K   5120            // 2 x 2560
#define KBUF   2560
#define SM_VT  10240           // 2 x 9216 (64 ch rows x 144B)
#define VTBUF  9216
#define SM_P   28672           // 4 warps x 16 rows x 144B = 9216
#define PWARP  2304
#define SMEM_TOTAL 37888

// ---- global scratch ----
__device__ float g_QPf[BB*NN*8];
__device__ int   g_maxk[BB][8];
__device__ __align__(16) __nv_bfloat16 g_Q16[BB*NN*32];
__device__ __align__(16) __nv_bfloat16 g_K16[BB*NN*32];
__device__ __align__(16) float g_Vf[BB*CC*NN];                // tf32-rounded, ch-major
__device__ __align__(16) float g_Opart[NSPLIT][BB][NN][CC];   // 8MB partials
__device__ float g_Spart[NSPLIT][BB][NN];

// ---- helpers ----
__device__ __forceinline__ uint32_t s2u(const void* p) {
    uint32_t a;
    asm("{ .reg .u64 t; cvta.to.shared.u64 t, %1; cvt.u32.u64 %0, t; }" : "=r"(a) : "l"(p));
    return a;
}
__device__ __forceinline__ float ex2f(float x) {
    float r; asm("ex2.approx.f32 %0, %1;" : "=f"(r) : "f"(x)); return r;
}
__device__ __forceinline__ uint32_t cvt2bf(float hi, float lo) {
    uint32_t r; asm("cvt.rn.bf16x2.f32 %0, %1, %2;" : "=r"(r) : "f"(hi), "f"(lo)); return r;
}
__device__ __forceinline__ uint32_t tf32r(float x) {
    uint32_t r; asm("cvt.rna.tf32.f32 %0, %1;" : "=r"(r) : "f"(x)); return r;
}
__device__ __forceinline__ void cpa16(uint32_t dst, const void* src) {
    asm volatile("cp.async.cg.shared.global [%0], [%1], 16;" :: "r"(dst), "l"(src));
}
__device__ __forceinline__ void ldsm4(uint32_t* r, uint32_t a) {
    asm volatile("ldmatrix.sync.aligned.m8n8.x4.shared.b16 {%0,%1,%2,%3}, [%4];"
        : "=r"(r[0]), "=r"(r[1]), "=r"(r[2]), "=r"(r[3]) : "r"(a));
}
__device__ __forceinline__ void mma16816(float* d, const uint32_t* a, const uint32_t* b) {
    asm volatile(
        "mma.sync.aligned.m16n8k16.row.col.f32.bf16.bf16.f32 "
        "{%0,%1,%2,%3}, {%4,%5,%6,%7}, {%8,%9}, {%0,%1,%2,%3};"
        : "+f"(d[0]), "+f"(d[1]), "+f"(d[2]), "+f"(d[3])
        : "r"(a[0]), "r"(a[1]), "r"(a[2]), "r"(a[3]), "r"(b[0]), "r"(b[1]));
}
__device__ __forceinline__ void mma1688t(float* d, const uint32_t* a, uint32_t b0, uint32_t b1) {
    asm volatile(
        "mma.sync.aligned.m16n8k8.row.col.f32.tf32.tf32.f32 "
        "{%0,%1,%2,%3}, {%4,%5,%6,%7}, {%8,%9}, {%0,%1,%2,%3};"
        : "+f"(d[0]), "+f"(d[1]), "+f"(d[2]), "+f"(d[3])
        : "r"(a[0]), "r"(a[1]), "r"(a[2]), "r"(a[3]), "r"(b0), "r"(b1));
}
__device__ __forceinline__ void sts64(uint32_t a, uint32_t v0, uint32_t v1) {
    asm volatile("st.shared.v2.b32 [%0], {%1, %2};" :: "r"(a), "r"(v0), "r"(v1));
}

// ---------------------------------------------------------------------------
// Prep: 1x1 convs -> packed bf16 Q/K + tf32 V (ch-major).
// 256 blocks x 320 threads: 64 pixels x 10 warp-groups, 2 pixels per thread.
//   g0 = q + Q pack, g1 = k + K pack + max|k|, g2..g9 = V 8ch each.
// ---------------------------------------------------------------------------
__global__ __launch_bounds__(320) void prep_kernel(
    const float* __restrict__ x,
    const float* __restrict__ Wq, const float* __restrict__ bq,
    const float* __restrict__ Wk, const float* __restrict__ bk,
    const float* __restrict__ Wv, const float* __restrict__ bv)
{
    __shared__ float xs[CC][PBLK];     // 16KB
    __shared__ float wv_s[CC][CC];     // 16KB
    __shared__ float wq_s[8][CC];
    __shared__ float wk_s[8][CC];
    __shared__ float bv_s[CC];
    __shared__ float bq_s[8], bk_s[8];

    const int b  = blockIdx.x >> 6;
    const int n0 = (blockIdx.x & 63) * PBLK;
    const int t  = threadIdx.x;

    for (int i = t; i < CC*PBLK; i += 320)
        xs[i >> 6][i & 63] = x[(b*CC + (i >> 6))*NN + n0 + (i & 63)];
    for (int i = t; i < CC*CC; i += 320) wv_s[i >> 6][i & 63] = Wv[i];
    for (int i = t; i < 8*CC;  i += 320) { wq_s[i >> 6][i & 63] = Wq[i]; wk_s[i >> 6][i & 63] = Wk[i]; }
    if (t < CC) bv_s[t] = bv[t];
    if (t < 8)  { bq_s[t] = bq[t]; bk_s[t] = bk[t]; }
    __syncthreads();

    const int g = t >> 5;        // warp id 0..9
    const int p = t & 31;        // pixels p and p+32

    if (g == 0) {
        float acc[2][8];
        #pragma unroll
        for (int d = 0; d < 8; d++) { acc[0][d] = 0.f; acc[1][d] = 0.f; }
        for (int c = 0; c < CC; c++) {
            float x0 = xs[c][p], x1 = xs[c][p + 32];
            #pragma unroll
            for (int d = 0; d < 8; d++) {
                acc[0][d] = fmaf(wq_s[d][c], x0, acc[0][d]);
                acc[1][d] = fmaf(wq_s[d][c], x1, acc[1][d]);
            }
        }
        #pragma unroll
        for (int u = 0; u < 2; u++) {
            const int n = n0 + p + 32*u;
            float qv[8];
            #pragma unroll
            for (int d = 0; d < 8; d++) qv[d] = acc[u][d] + bq_s[d];
            #pragma unroll
            for (int d = 0; d < 8; d++) g_QPf[(size_t)(b*NN + n)*8 + d] = qv[d];

            uint32_t u16[16];
            float lo[8];
            #pragma unroll
            for (int i = 0; i < 4; i++) {
                uint32_t hh = cvt2bf(qv[2*i+1], qv[2*i]);
                u16[i] = hh;
                lo[2*i]   = qv[2*i]   - __uint_as_float(hh << 16);
                lo[2*i+1] = qv[2*i+1] - __uint_as_float(hh & 0xFFFF0000u);
            }
            u16[4] = u16[0];
            u16[5] = u16[0]; u16[6] = u16[1]; u16[7] = u16[2]; u16[8] = u16[3];
            #pragma unroll
            for (int i = 0; i < 4; i++) u16[9+i] = cvt2bf(lo[2*i+1], lo[2*i]);
            u16[13] = u16[9];
            u16[14] = 0; u16[15] = 0;
            uint4* dst = (uint4*)&g_Q16[(size_t)(b*NN + n)*32];
            dst[0] = make_uint4(u16[0],u16[1],u16[2],u16[3]);
            dst[1] = make_uint4(u16[4],u16[5],u16[6],u16[7]);
            dst[2] = make_uint4(u16[8],u16[9],u16[10],u16[11]);
            dst[3] = make_uint4(u16[12],u16[13],u16[14],u16[15]);
        }
    } else if (g == 1) {
        float acc[2][8];
        #pragma unroll
        for (int d = 0; d < 8; d++) { acc[0][d] = 0.f; acc[1][d] = 0.f; }
        for (int c = 0; c < CC; c++) {
            float x0 = xs[c][p], x1 = xs[c][p + 32];
            #pragma unroll
            for (int d = 0; d < 8; d++) {
                acc[0][d] = fmaf(wk_s[d][c], x0, acc[0][d]);
                acc[1][d] = fmaf(wk_s[d][c], x1, acc[1][d]);
            }
        }
        float kv[2][8];
        #pragma unroll
        for (int u = 0; u < 2; u++)
            #pragma unroll
            for (int d = 0; d < 8; d++) kv[u][d] = acc[u][d] + bk_s[d];

        #pragma unroll
        for (int d = 0; d < 8; d++) {
            float a = fmaxf(fabsf(kv[0][d]), fabsf(kv[1][d]));
            #pragma unroll
            for (int o = 16; o > 0; o >>= 1)
                a = fmaxf(a, __shfl_xor_sync(0xffffffffu, a, o));
            if (p == 0) atomicMax(&g_maxk[b][d], __float_as_int(a));
        }

        #pragma unroll
        for (int u = 0; u < 2; u++) {
            const int n = n0 + p + 32*u;
            uint32_t u16[16];
            float lo[8];
            #pragma unroll
            for (int i = 0; i < 4; i++) {
                uint32_t hh = cvt2bf(kv[u][2*i+1], kv[u][2*i]);
                u16[i] = hh;
                lo[2*i]   = kv[u][2*i]   - __uint_as_float(hh << 16);
                lo[2*i+1] = kv[u][2*i+1] - __uint_as_float(hh & 0xFFFF0000u);
            }
            float colc = (float)(n % WDIM) - 31.5f;   // exact in bf16
            float rowc = (float)(n / WDIM) - 31.5f;
            u16[4] = cvt2bf(rowc, colc);
            #pragma unroll
            for (int i = 0; i < 4; i++) u16[5+i] = cvt2bf(lo[2*i+1], lo[2*i]);
            u16[9] = u16[0]; u16[10] = u16[1]; u16[11] = u16[2]; u16[12] = u16[3];
            u16[13] = u16[4];
            u16[14] = 0; u16[15] = 0;
            uint4* dst = (uint4*)&g_K16[(size_t)(b*NN + n)*32];
            dst[0] = make_uint4(u16[0],u16[1],u16[2],u16[3]);
            dst[1] = make_uint4(u16[4],u16[5],u16[6],u16[7]);
            dst[2] = make_uint4(u16[8],u16[9],u16[10],u16[11]);
            dst[3] = make_uint4(u16[12],u16[13],u16[14],u16[15]);
        }
    } else {
        const int e0 = (g - 2) * 8;
        float acc[2][8];
        #pragma unroll
        for (int e = 0; e < 8; e++) { acc[0][e] = 0.f; acc[1][e] = 0.f; }
        for (int c = 0; c < CC; c++) {
            float x0 = xs[c][p], x1 = xs[c][p + 32];
            #pragma unroll
            for (int e = 0; e < 8; e++) {
                acc[0][e] = fmaf(wv_s[e0 + e][c], x0, acc[0][e]);
                acc[1][e] = fmaf(wv_s[e0 + e][c], x1, acc[1][e]);
            }
        }
        #pragma unroll
        for (int u = 0; u < 2; u++) {
            const int n = n0 + p + 32*u;
            #pragma unroll
            for (int e = 0; e < 8; e++) {
                float v = acc[u][e] + bv_s[e0 + e];
                g_Vf[(size_t)(b*CC + e0 + e)*NN + n] = __uint_as_float(tf32r(v));
            }
        }
    }
}

// ---------------------------------------------------------------------------
// Split-K mma.sync flash attention: 512 CTAs, 128 threads (4 warps x 16 q rows),
// 32-key tiles. Scores: packed 32-dim bf16 (3-term hi/lo). PV: single-term tf32
// (P staged via warp-private smem, V ch-major fp32/tf32, B-frags via ldmatrix).
// Bound-based softmax -> partials add linearly across splits.
// ---------------------------------------------------------------------------
#define STAGE(tile, bbuf) do {                                              \
    int m0s = (tile)*KTILE;                                                 \
    { int row = t >> 2, seg = t & 3;                                        \
      cpa16(sb + SM_K + (bbuf)*KBUF + row*KSTRIDE + seg*16,                 \
            &g_K16[(size_t)(b*NN + m0s + row)*32 + seg*8]); }               \
    _Pragma("unroll")                                                       \
    for (int j5 = 0; j5 < 4; j5++) {                                        \
        int id = t + 128*j5; int row = id >> 3, seg = id & 7;               \
        cpa16(sb + SM_VT + (bbuf)*VTBUF + row*VTSTRIDE + seg*16,            \
              &g_Vf[(size_t)(b*CC + row)*NN + m0s + seg*4]);                \
    }                                                                       \
} while (0)

__global__ __launch_bounds__(128, 4) void attn_kernel()
{
    extern __shared__ char smem[];
    const uint32_t sb = s2u(smem);
    const int t = threadIdx.x;
    const int w = t >> 5;
    const int l = t & 31;
    const int sp = blockIdx.x >> 8;
    const int b  = (blockIdx.x >> 6) & 3;
    const int n0 = (blockIdx.x & 63) * MQ;
    const int qr0 = w * 16;
    const int t0 = sp * TILES_PER_SPLIT;

    // stage Q (plain loads): 64 rows x 64B
    #pragma unroll
    for (int j = 0; j < 2; j++) {
        int id = t + 128*j;
        int row = id >> 2, seg = id & 3;
        uint4 v = *(const uint4*)&g_Q16[(size_t)(b*NN + n0 + row)*32 + seg*8];
        *(uint4*)(smem + SM_Q + row*QSTRIDE + seg*16) = v;
    }

    // prefetch first tile of this split
    STAGE(t0, 0);
    asm volatile("cp.async.commit_group;" ::: "memory");

    // softmax bounds for this lane's two query rows
    float bndA, bndB;
    {
        int rA = n0 + qr0 + (l >> 2);
        const float* qa = &g_QPf[(size_t)(b*NN + rA)*8];
        const float* qb = qa + 8*8;
        float ba = 0.f, bb2 = 0.f;
        #pragma unroll
        for (int d = 0; d < 8; d++) {
            float mk = __int_as_float(g_maxk[b][d]);
            float qda = fabsf(qa[d]), qdb = fabsf(qb[d]);
            ba  = fmaf(qda, mk, ba);
            bb2 = fmaf(qdb, mk, bb2);
            if (d < 2) { ba += 31.5f*qda; bb2 += 31.5f*qdb; }
        }
        bndA = ba * L2E; bndB = bb2 * L2E;
    }

    __syncthreads();   // Q staged

    uint32_t qA[4], qB[4];
    {
        uint32_t qa = sb + SM_Q + (qr0 + (l & 7) + ((l >> 3) & 1)*8)*QSTRIDE + (l >> 4)*16;
        ldsm4(qA, qa);
        ldsm4(qB, qa + 32);
    }

    // warp-private P tile base + lane-fixed ldmatrix addresses
    const uint32_t pbase = sb + SM_P + w*PWARP;
    // A-frag ldmatrix row address (per kt add kt*32 + (i>>1)*16)
    const uint32_t pa_row = pbase + (((l >> 3) & 1)*8 + (l & 7))*VTSTRIDE + (l >> 4)*16;
    // B-frag ldmatrix: lane i = l>>3 (matrix), j = l&7 (row)
    const uint32_t vt_lane_off = (l & 7)*VTSTRIDE + (l >> 3)*16;

    float O[8][4];
    #pragma unroll
    for (int j = 0; j < 8; j++) { O[j][0]=0.f; O[j][1]=0.f; O[j][2]=0.f; O[j][3]=0.f; }
    float sumA = 0.f, sumB = 0.f;

    for (int ti = 0; ti < TILES_PER_SPLIT; ti++) {
        const int bbuf = ti & 1;
        if (ti + 1 < TILES_PER_SPLIT) STAGE(t0 + ti + 1, (ti + 1) & 1);
        asm volatile("cp.async.commit_group;" ::: "memory");
        asm volatile("cp.async.wait_group 1;" ::: "memory");
        __syncthreads();

        // ---- scores: single packed 32-dim bf16 contraction ----
        const uint32_t kbase = sb + SM_K + bbuf*KBUF;
        float S[4][4];
        #pragma unroll
        for (int p2 = 0; p2 < 2; p2++) {
            uint32_t ka = kbase + (p2*16 + (l & 7) + (l >> 4)*8)*KSTRIDE + ((l >> 3) & 1)*16;
            uint32_t kA[4], kB[4];
            ldsm4(kA, ka);
            ldsm4(kB, ka + 32);
            float* s0 = S[2*p2]; float* s1 = S[2*p2+1];
            s0[0]=0.f; s0[1]=0.f; s0[2]=0.f; s0[3]=0.f;
            s1[0]=0.f; s1[1]=0.f; s1[2]=0.f; s1[3]=0.f;
            mma16816(s0, qA, kA);     mma16816(s0, qB, kB);
            mma16816(s1, qA, kA + 2); mma16816(s1, qB, kB + 2);
        }

        // ---- exp (bound-shifted, no row max) ----
        #pragma unroll
        for (int j = 0; j < 4; j++) {
            S[j][0] = ex2f(fmaf(S[j][0], L2E, -bndA));
            S[j][1] = ex2f(fmaf(S[j][1], L2E, -bndA));
            S[j][2] = ex2f(fmaf(S[j][2], L2E, -bndB));
            S[j][3] = ex2f(fmaf(S[j][3], L2E, -bndB));
            sumA += S[j][0] + S[j][1];
            sumB += S[j][2] + S[j][3];
        }

        // ---- stage P (tf32) into warp-private smem: rows=16 q, cols=32 keys ----
        #pragma unroll
        for (int j = 0; j < 4; j++) {
            uint32_t p0 = tf32r(S[j][0]), p1 = tf32r(S[j][1]);
            uint32_t p2v = tf32r(S[j][2]), p3 = tf32r(S[j][3]);
            uint32_t ad = pbase + (l >> 2)*VTSTRIDE + (j*8 + 2*(l & 3))*4;
            sts64(ad, p0, p1);
            sts64(ad + 8*VTSTRIDE, p2v, p3);
        }
        __syncwarp();

        // ---- A-frags for 4 k-steps of 8 keys ----
        uint32_t afr[4][4];
        #pragma unroll
        for (int kt = 0; kt < 4; kt++)
            ldsm4(afr[kt], pa_row + kt*32);

        // ---- PV: O += P(tf32) x V(tf32), B via ldmatrix on ch-major V ----
        const uint32_t vtb = sb + SM_VT + bbuf*VTBUF + vt_lane_off;
        #pragma unroll
        for (int ktp = 0; ktp < 2; ktp++) {
            #pragma unroll
            for (int cp = 0; cp < 8; cp++) {
                uint32_t bfr[4];
                ldsm4(bfr, vtb + (cp*8)*VTSTRIDE + ktp*64);
                mma1688t(O[cp], afr[2*ktp],     bfr[0], bfr[1]);
                mma1688t(O[cp], afr[2*ktp + 1], bfr[2], bfr[3]);
            }
        }
        __syncthreads();
    }

    // ---- epilogue: write UNNORMALIZED partials (adds across splits) ----
    sumA += __shfl_xor_sync(0xffffffffu, sumA, 1);
    sumA += __shfl_xor_sync(0xffffffffu, sumA, 2);
    sumB += __shfl_xor_sync(0xffffffffu, sumB, 1);
    sumB += __shfl_xor_sync(0xffffffffu, sumB, 2);

    const int nA = n0 + qr0 + (l >> 2);
    if ((l & 3) == 0) {
        g_Spart[sp][b][nA]     = sumA;
        g_Spart[sp][b][nA + 8] = sumB;
    }
    #pragma unroll
    for (int j = 0; j < 8; j++) {
        int ch = j*8 + (l & 3)*2;
        *(float2*)&g_Opart[sp][b][nA][ch]     = make_float2(O[j][0], O[j][1]);
        *(float2*)&g_Opart[sp][b][nA + 8][ch] = make_float2(O[j][2], O[j][3]);
    }
}

// ---------------------------------------------------------------------------
// Reduce: out[b][c][n] = (O0+O1)[b][n][c] / (S0+S1)[b][n], coalesced via
// 64x64 smem transpose.  256 blocks x 256 threads.
// ---------------------------------------------------------------------------
__global__ __launch_bounds__(256) void reduce_kernel(float* __restrict__ out)
{
    __shared__ float tile[CC][65];
    __shared__ float inv_s[64];
    const int b  = blockIdx.x >> 6;
    const int n0 = (blockIdx.x & 63) * 64;
    const int t  = threadIdx.x;

    if (t < 64)
        inv_s[t] = 1.0f / (g_Spart[0][b][n0 + t] + g_Spart[1][b][n0 + t]);
    __syncthreads();

    #pragma unroll
    for (int j = 0; j < 4; j++) {
        int idx = t + 256*j;
        int r = idx >> 4, c4 = (idx & 15)*4;
        float4 a0 = *(const float4*)&g_Opart[0][b][n0 + r][c4];
        float4 a1 = *(const float4*)&g_Opart[1][b][n0 + r][c4];
        float iv = inv_s[r];
        tile[c4    ][r] = (a0.x + a1.x) * iv;
        tile[c4 + 1][r] = (a0.y + a1.y) * iv;
        tile[c4 + 2][r] = (a0.z + a1.z) * iv;
        tile[c4 + 3][r] = (a0.w + a1.w) * iv;
    }
    __syncthreads();

    #pragma unroll
    for (int j = 0; j < 4; j++) {
        int idx = t + 256*j;
        int c = idx >> 4, nn = (idx & 15)*4;
        // scalar LDS (row stride 65 floats not 16B-aligned); vector STG
        float4 vv = make_float4(tile[c][nn], tile[c][nn + 1],
                                tile[c][nn + 2], tile[c][nn + 3]);
        *(float4*)&out[(size_t)(b*CC + c)*NN + n0 + nn] = vv;
    }
}

extern "C" void kernel_launch(void* const* d_in, const int* in_sizes, int n_in,
                              void* d_out, int out_size)
{
    const float* x  = (const float*)d_in[0];
    const float* Wq = (const float*)d_in[1];
    const float* bq = (const float*)d_in[2];
    const float* Wk = (const float*)d_in[3];
    const float* bk = (const float*)d_in[4];
    const float* Wv = (const float*)d_in[5];
    const float* bv = (const float*)d_in[6];
    float* out = (float*)d_out;

    prep_kernel<<<BB*(NN/PBLK), 320>>>(x, Wq, bq, Wk, bk, Wv, bv);
    attn_kernel<<<NSPLIT*BB*(NN/MQ), 128, SMEM_TOTAL>>>();
    reduce_kernel<<<BB*(NN/64), 256>>>(out);
}

// round 13
// speedup vs baseline: 1.0129x; 1.0129x over previous
#include <cuda_runtime.h>
#include <cuda_bf16.h>
#include <stdint.h>

#define BB 4
#define CC 64
#define WDIM 64
#define NN 4096
#define MQ 64
#define KTILE 32
#define NSPLIT 2
#define TILES_PER_SPLIT (NN/KTILE/NSPLIT)   // 64
#define L2E 1.44269504088896f
#define PBLK 32

#define QSTRIDE 80
#define KSTRIDE 80
#define VSTRIDE 144
// triple-buffered K/V
#define SM_Q   0                 // 64 x 80 = 5120
#define SM_K   5120              // 3 x 2560
#define KBUF   2560
#define SM_VH  12800             // 3 x 4608
#define VBUF   4608
#define SM_VL  26624             // 3 x 4608
#define SMEM_TOTAL 40448

// ---- global scratch ----
__device__ float g_QPf[BB*NN*8];
__device__ int   g_maxk[BB][8];
__device__ __align__(16) __nv_bfloat16 g_Q16[BB*NN*32];
__device__ __align__(16) __nv_bfloat16 g_K16[BB*NN*32];
__device__ __align__(16) __nv_bfloat16 g_Vh[BB*NN*CC];
__device__ __align__(16) __nv_bfloat16 g_Vl[BB*NN*CC];
__device__ __align__(16) float g_Opart[NSPLIT][BB][NN][CC];   // 8MB partials
__device__ float g_Spart[NSPLIT][BB][NN];

// ---- helpers ----
__device__ __forceinline__ uint32_t s2u(const void* p) {
    uint32_t a;
    asm("{ .reg .u64 t; cvta.to.shared.u64 t, %1; cvt.u32.u64 %0, t; }" : "=r"(a) : "l"(p));
    return a;
}
__device__ __forceinline__ float ex2f(float x) {
    float r; asm("ex2.approx.f32 %0, %1;" : "=f"(r) : "f"(x)); return r;
}
// packs: lower 16 bits = lo arg, upper 16 = hi arg
__device__ __forceinline__ uint32_t cvt2bf(float hi, float lo) {
    uint32_t r; asm("cvt.rn.bf16x2.f32 %0, %1, %2;" : "=r"(r) : "f"(hi), "f"(lo)); return r;
}
__device__ __forceinline__ void cpa16(uint32_t dst, const void* src) {
    asm volatile("cp.async.cg.shared.global [%0], [%1], 16;" :: "r"(dst), "l"(src));
}
__device__ __forceinline__ void ldsm4(uint32_t* r, uint32_t a) {
    asm volatile("ldmatrix.sync.aligned.m8n8.x4.shared.b16 {%0,%1,%2,%3}, [%4];"
        : "=r"(r[0]), "=r"(r[1]), "=r"(r[2]), "=r"(r[3]) : "r"(a));
}
__device__ __forceinline__ void ldsm4t(uint32_t* r, uint32_t a) {
    asm volatile("ldmatrix.sync.aligned.m8n8.x4.trans.shared.b16 {%0,%1,%2,%3}, [%4];"
        : "=r"(r[0]), "=r"(r[1]), "=r"(r[2]), "=r"(r[3]) : "r"(a));
}
__device__ __forceinline__ void mma16816(float* d, const uint32_t* a, const uint32_t* b) {
    asm volatile(
        "mma.sync.aligned.m16n8k16.row.col.f32.bf16.bf16.f32 "
        "{%0,%1,%2,%3}, {%4,%5,%6,%7}, {%8,%9}, {%0,%1,%2,%3};"
        : "+f"(d[0]), "+f"(d[1]), "+f"(d[2]), "+f"(d[3])
        : "r"(a[0]), "r"(a[1]), "r"(a[2]), "r"(a[3]), "r"(b[0]), "r"(b[1]));
}

// ---------------------------------------------------------------------------
// Prep: 1x1 convs -> packed bf16 operand tensors.
// 512 blocks x 320 threads: 32 pixels x 10 warp-groups
//   g0 = q (8ch) + Q pack, g1 = k (8ch) + K pack + max|k|, g2..g9 = V 8ch each.
// Packed 32-dim score layout (per row):
//  Q: [0-7]=qh, [8]=qh0,[9]=qh1, [10-17]=qh, [18-25]=ql, [26]=ql0,[27]=ql1, [28-31]=0
//  K: [0-7]=kh, [8]=col,[9]=row, [10-17]=kl, [18-25]=kh, [26]=col,[27]=row, [28-31]=0
// ---------------------------------------------------------------------------
__global__ __launch_bounds__(320) void prep_kernel(
    const float* __restrict__ x,
    const float* __restrict__ Wq, const float* __restrict__ bq,
    const float* __restrict__ Wk, const float* __restrict__ bk,
    const float* __restrict__ Wv, const float* __restrict__ bv)
{
    __shared__ float xs[CC][PBLK];     // 8KB
    __shared__ float wv_s[CC][CC];     // 16KB
    __shared__ float wq_s[8][CC];
    __shared__ float wk_s[8][CC];
    __shared__ float bv_s[CC];
    __shared__ float bq_s[8], bk_s[8];

    const int b  = blockIdx.x >> 7;
    const int n0 = (blockIdx.x & 127) * PBLK;
    const int t  = threadIdx.x;

    for (int i = t; i < CC*PBLK; i += 320)
        xs[i >> 5][i & 31] = x[(b*CC + (i >> 5))*NN + n0 + (i & 31)];
    for (int i = t; i < CC*CC; i += 320) wv_s[i >> 6][i & 63] = Wv[i];
    for (int i = t; i < 8*CC;  i += 320) { wq_s[i >> 6][i & 63] = Wq[i]; wk_s[i >> 6][i & 63] = Wk[i]; }
    if (t < CC) bv_s[t] = bv[t];
    if (t < 8)  { bq_s[t] = bq[t]; bk_s[t] = bk[t]; }
    __syncthreads();

    const int g = t >> 5;        // warp id 0..9
    const int p = t & 31;
    const int n = n0 + p;

    if (g == 0) {
        // ---- q projection + Q pack ----
        float acc[8];
        #pragma unroll
        for (int d = 0; d < 8; d++) acc[d] = 0.f;
        for (int c = 0; c < CC; c++) {
            float xc = xs[c][p];
            #pragma unroll
            for (int d = 0; d < 8; d++) acc[d] = fmaf(wq_s[d][c], xc, acc[d]);
        }
        float qv[8];
        #pragma unroll
        for (int d = 0; d < 8; d++) qv[d] = acc[d] + bq_s[d];
        #pragma unroll
        for (int d = 0; d < 8; d++) g_QPf[(size_t)(b*NN + n)*8 + d] = qv[d];

        uint32_t u[16];
        float lo[8];
        #pragma unroll
        for (int i = 0; i < 4; i++) {
            uint32_t hh = cvt2bf(qv[2*i+1], qv[2*i]);
            u[i] = hh;
            lo[2*i]   = qv[2*i]   - __uint_as_float(hh << 16);
            lo[2*i+1] = qv[2*i+1] - __uint_as_float(hh & 0xFFFF0000u);
        }
        u[4] = u[0];
        u[5] = u[0]; u[6] = u[1]; u[7] = u[2]; u[8] = u[3];
        #pragma unroll
        for (int i = 0; i < 4; i++) u[9+i] = cvt2bf(lo[2*i+1], lo[2*i]);
        u[13] = u[9];
        u[14] = 0; u[15] = 0;
        uint4* dst = (uint4*)&g_Q16[(size_t)(b*NN + n)*32];
        dst[0] = make_uint4(u[0],u[1],u[2],u[3]);
        dst[1] = make_uint4(u[4],u[5],u[6],u[7]);
        dst[2] = make_uint4(u[8],u[9],u[10],u[11]);
        dst[3] = make_uint4(u[12],u[13],u[14],u[15]);
    } else if (g == 1) {
        // ---- k projection + max|k| + K pack ----
        float acc[8];
        #pragma unroll
        for (int d = 0; d < 8; d++) acc[d] = 0.f;
        for (int c = 0; c < CC; c++) {
            float xc = xs[c][p];
            #pragma unroll
            for (int d = 0; d < 8; d++) acc[d] = fmaf(wk_s[d][c], xc, acc[d]);
        }
        float kv[8];
        #pragma unroll
        for (int d = 0; d < 8; d++) kv[d] = acc[d] + bk_s[d];

        #pragma unroll
        for (int d = 0; d < 8; d++) {
            float a = fabsf(kv[d]);
            #pragma unroll
            for (int o = 16; o > 0; o >>= 1)
                a = fmaxf(a, __shfl_xor_sync(0xffffffffu, a, o));
            if (p == 0) atomicMax(&g_maxk[b][d], __float_as_int(a));
        }

        uint32_t u[16];
        float lo[8];
        #pragma unroll
        for (int i = 0; i < 4; i++) {
            uint32_t hh = cvt2bf(kv[2*i+1], kv[2*i]);
            u[i] = hh;
            lo[2*i]   = kv[2*i]   - __uint_as_float(hh << 16);
            lo[2*i+1] = kv[2*i+1] - __uint_as_float(hh & 0xFFFF0000u);
        }
        float colc = (float)(n % WDIM) - 31.5f;   // exact in bf16
        float rowc = (float)(n / WDIM) - 31.5f;
        u[4] = cvt2bf(rowc, colc);
        #pragma unroll
        for (int i = 0; i < 4; i++) u[5+i] = cvt2bf(lo[2*i+1], lo[2*i]);
        u[9] = u[0]; u[10] = u[1]; u[11] = u[2]; u[12] = u[3];
        u[13] = u[4];
        u[14] = 0; u[15] = 0;
        uint4* dst = (uint4*)&g_K16[(size_t)(b*NN + n)*32];
        dst[0] = make_uint4(u[0],u[1],u[2],u[3]);
        dst[1] = make_uint4(u[4],u[5],u[6],u[7]);
        dst[2] = make_uint4(u[8],u[9],u[10],u[11]);
        dst[3] = make_uint4(u[12],u[13],u[14],u[15]);
    } else {
        // ---- V projection: 8 channels per warp-group ----
        const int e0 = (g - 2) * 8;
        float acc[8];
        #pragma unroll
        for (int e = 0; e < 8; e++) acc[e] = 0.f;
        for (int c = 0; c < CC; c++) {
            float xc = xs[c][p];
            #pragma unroll
            for (int e = 0; e < 8; e++) acc[e] = fmaf(wv_s[e0 + e][c], xc, acc[e]);
        }
        const size_t gbase = (size_t)(b*NN + n)*CC + e0;
        #pragma unroll
        for (int e = 0; e < 8; e++) {
            float v = acc[e] + bv_s[e0 + e];
            __nv_bfloat16 vh = __float2bfloat16(v);
            g_Vh[gbase + e] = vh;
            g_Vl[gbase + e] = __float2bfloat16(v - __bfloat162float(vh));
        }
    }
}

// ---------------------------------------------------------------------------
// Split-K mma.sync flash attention: 512 CTAs (2 splits x 4 b x 64 qtiles),
// 128 threads (4 warps x 16 query rows), 32-key tiles, packed 32-dim score
// contraction, bound-based softmax -> partials add linearly across splits.
// Triple-buffered K/V pipeline: ONE __syncthreads per tile.
// ---------------------------------------------------------------------------
#define STAGE(tile, bbuf) do {                                              \
    int m0s = (tile)*KTILE;                                                 \
    { int row = t >> 2, seg = t & 3;                                        \
      cpa16(sb + SM_K + (bbuf)*KBUF + row*KSTRIDE + seg*16,                 \
            &g_K16[(size_t)(b*NN + m0s + row)*32 + seg*8]); }               \
    _Pragma("unroll")                                                       \
    for (int j5 = 0; j5 < 2; j5++) {                                        \
        int id = t + 128*j5; int row = id >> 3, seg = id & 7;               \
        cpa16(sb + SM_VH + (bbuf)*VBUF + row*VSTRIDE + seg*16,              \
              &g_Vh[(size_t)(b*NN + m0s + row)*CC + seg*8]);                \
        cpa16(sb + SM_VL + (bbuf)*VBUF + row*VSTRIDE + seg*16,              \
              &g_Vl[(size_t)(b*NN + m0s + row)*CC + seg*8]);                \
    }                                                                       \
} while (0)

__global__ __launch_bounds__(128, 4) void attn_kernel()
{
    extern __shared__ char smem[];
    const uint32_t sb = s2u(smem);
    const int t = threadIdx.x;
    const int w = t >> 5;
    const int l = t & 31;
    const int sp = blockIdx.x >> 8;
    const int b  = (blockIdx.x >> 6) & 3;
    const int n0 = (blockIdx.x & 63) * MQ;
    const int qr0 = w * 16;
    const int t0 = sp * TILES_PER_SPLIT;

    // stage Q (plain loads): 64 rows x 64B
    #pragma unroll
    for (int j = 0; j < 2; j++) {
        int id = t + 128*j;
        int row = id >> 2, seg = id & 3;
        uint4 v = *(const uint4*)&g_Q16[(size_t)(b*NN + n0 + row)*32 + seg*8];
        *(uint4*)(smem + SM_Q + row*QSTRIDE + seg*16) = v;
    }

    // prefetch first tile of this split into buffer 0
    STAGE(t0, 0);
    asm volatile("cp.async.commit_group;" ::: "memory");

    // softmax bounds for this lane's two query rows
    float bndA, bndB;
    {
        int rA = n0 + qr0 + (l >> 2);
        const float* qa = &g_QPf[(size_t)(b*NN + rA)*8];
        const float* qb = qa + 8*8;
        float ba = 0.f, bb2 = 0.f;
        #pragma unroll
        for (int d = 0; d < 8; d++) {
            float mk = __int_as_float(g_maxk[b][d]);
            float qda = fabsf(qa[d]), qdb = fabsf(qb[d]);
            ba  = fmaf(qda, mk, ba);
            bb2 = fmaf(qdb, mk, bb2);
            if (d < 2) { ba += 31.5f*qda; bb2 += 31.5f*qdb; }
        }
        bndA = ba * L2E; bndB = bb2 * L2E;
    }

    __syncthreads();   // Q staged

    uint32_t qA[4], qB[4];
    {
        uint32_t qa = sb + SM_Q + (qr0 + (l & 7) + ((l >> 3) & 1)*8)*QSTRIDE + (l >> 4)*16;
        ldsm4(qA, qa);
        ldsm4(qB, qa + 32);
    }

    float O[8][4];
    #pragma unroll
    for (int j = 0; j < 8; j++) { O[j][0]=0.f; O[j][1]=0.f; O[j][2]=0.f; O[j][3]=0.f; }
    float sumA = 0.f, sumB = 0.f;

    int cb = 0, nb = 1;   // current / next buffer (mod 3)
    for (int ti = 0; ti < TILES_PER_SPLIT; ti++) {
        if (ti + 1 < TILES_PER_SPLIT) STAGE(t0 + ti + 1, nb);
        asm volatile("cp.async.commit_group;" ::: "memory");
        asm volatile("cp.async.wait_group 1;" ::: "memory");
        __syncthreads();   // single barrier per tile (triple buffer makes WAR safe)

        // ---- scores: single packed 32-dim contraction ----
        const uint32_t kbase = sb + SM_K + cb*KBUF;
        float S[4][4];
        #pragma unroll
        for (int p2 = 0; p2 < 2; p2++) {
            uint32_t ka = kbase + (p2*16 + (l & 7) + (l >> 4)*8)*KSTRIDE + ((l >> 3) & 1)*16;
            uint32_t kA[4], kB[4];
            ldsm4(kA, ka);
            ldsm4(kB, ka + 32);
            float* s0 = S[2*p2]; float* s1 = S[2*p2+1];
            s0[0]=0.f; s0[1]=0.f; s0[2]=0.f; s0[3]=0.f;
            s1[0]=0.f; s1[1]=0.f; s1[2]=0.f; s1[3]=0.f;
            mma16816(s0, qA, kA);     mma16816(s0, qB, kB);
            mma16816(s1, qA, kA + 2); mma16816(s1, qB, kB + 2);
        }

        // ---- exp (bound-shifted, no row max) ----
        #pragma unroll
        for (int j = 0; j < 4; j++) {
            S[j][0] = ex2f(fmaf(S[j][0], L2E, -bndA));
            S[j][1] = ex2f(fmaf(S[j][1], L2E, -bndA));
            S[j][2] = ex2f(fmaf(S[j][2], L2E, -bndB));
            S[j][3] = ex2f(fmaf(S[j][3], L2E, -bndB));
            sumA += S[j][0] + S[j][1];
            sumB += S[j][2] + S[j][3];
        }

        // ---- PV: O += ph*vh + pl*vh + ph*vl ----
        const uint32_t vhb = sb + SM_VH + cb*VBUF;
        const uint32_t vlb = sb + SM_VL + cb*VBUF;
        #pragma unroll
        for (int kt = 0; kt < 2; kt++) {
            const float* sa = S[2*kt];
            const float* sc = S[2*kt+1];
            uint32_t ph[4], pl[4];
            ph[0] = cvt2bf(sa[1], sa[0]);
            ph[1] = cvt2bf(sa[3], sa[2]);
            ph[2] = cvt2bf(sc[1], sc[0]);
            ph[3] = cvt2bf(sc[3], sc[2]);
            #pragma unroll
            for (int i = 0; i < 4; i++) {
                const float* s = (i < 2) ? sa : sc;
                int e = (i & 1)*2;
                float l0 = s[e]   - __uint_as_float(ph[i] << 16);
                float l1 = s[e+1] - __uint_as_float(ph[i] & 0xFFFF0000u);
                pl[i] = cvt2bf(l1, l0);
            }
            uint32_t rowoff = (kt*16 + (l & 7) + ((l >> 3) & 1)*8)*VSTRIDE + (l >> 4)*16;
            #pragma unroll
            for (int cp = 0; cp < 4; cp++) {
                uint32_t vh[4], vl[4];
                ldsm4t(vh, vhb + rowoff + cp*32);
                ldsm4t(vl, vlb + rowoff + cp*32);
                float* o0 = O[2*cp]; float* o1 = O[2*cp+1];
                mma16816(o0, ph, vh);     mma16816(o0, pl, vh);     mma16816(o0, ph, vl);
                mma16816(o1, ph, vh + 2); mma16816(o1, pl, vh + 2); mma16816(o1, ph, vl + 2);
            }
        }

        cb = nb;
        nb = (nb == 2) ? 0 : nb + 1;
    }

    // ---- epilogue: write UNNORMALIZED partials (adds across splits) ----
    sumA += __shfl_xor_sync(0xffffffffu, sumA, 1);
    sumA += __shfl_xor_sync(0xffffffffu, sumA, 2);
    sumB += __shfl_xor_sync(0xffffffffu, sumB, 1);
    sumB += __shfl_xor_sync(0xffffffffu, sumB, 2);

    const int nA = n0 + qr0 + (l >> 2);
    if ((l & 3) == 0) {
        g_Spart[sp][b][nA]     = sumA;
        g_Spart[sp][b][nA + 8] = sumB;
    }
    #pragma unroll
    for (int j = 0; j < 8; j++) {
        int ch = j*8 + (l & 3)*2;
        *(float2*)&g_Opart[sp][b][nA][ch]     = make_float2(O[j][0], O[j][1]);
        *(float2*)&g_Opart[sp][b][nA + 8][ch] = make_float2(O[j][2], O[j][3]);
    }
}

// ---------------------------------------------------------------------------
// Reduce: out[b][c][n] = (O0+O1)[b][n][c] / (S0+S1)[b][n], coalesced via
// 64x64 smem transpose.  256 blocks x 256 threads.
// ---------------------------------------------------------------------------
__global__ __launch_bounds__(256) void reduce_kernel(float* __restrict__ out)
{
    __shared__ float tile[CC][65];
    __shared__ float inv_s[64];
    const int b  = blockIdx.x >> 6;
    const int n0 = (blockIdx.x & 63) * 64;
    const int t  = threadIdx.x;

    if (t < 64)
        inv_s[t] = 1.0f / (g_Spart[0][b][n0 + t] + g_Spart[1][b][n0 + t]);
    __syncthreads();

    #pragma unroll
    for (int j = 0; j < 4; j++) {
        int idx = t + 256*j;
        int r = idx >> 4, c4 = (idx & 15)*4;
        float4 a0 = *(const float4*)&g_Opart[0][b][n0 + r][c4];
        float4 a1 = *(const float4*)&g_Opart[1][b][n0 + r][c4];
        float iv = inv_s[r];
        tile[c4    ][r] = (a0.x + a1.x) * iv;
        tile[c4 + 1][r] = (a0.y + a1.y) * iv;
        tile[c4 + 2][r] = (a0.z + a1.z) * iv;
        tile[c4 + 3][r] = (a0.w + a1.w) * iv;
    }
    __syncthreads();

    #pragma unroll
    for (int j = 0; j < 4; j++) {
        int idx = t + 256*j;
        int c = idx >> 4, nn = (idx & 15)*4;
        // scalar LDS (row stride 65 floats not 16B-aligned); vector STG
        float4 vv = make_float4(tile[c][nn], tile[c][nn + 1],
                                tile[c][nn + 2], tile[c][nn + 3]);
        *(float4*)&out[(size_t)(b*CC + c)*NN + n0 + nn] = vv;
    }
}

extern "C" void kernel_launch(void* const* d_in, const int* in_sizes, int n_in,
                              void* d_out, int out_size)
{
    const float* x  = (const float*)d_in[0];
    const float* Wq = (const float*)d_in[1];
    const float* bq = (const float*)d_in[2];
    const float* Wk = (const float*)d_in[3];
    const float* bk = (const float*)d_in[4];
    const float* Wv = (const float*)d_in[5];
    const float* bv = (const float*)d_in[6];
    float* out = (float*)d_out;

    prep_kernel<<<BB*(NN/PBLK), 320>>>(x, Wq, bq, Wk, bk, Wv, bv);
    attn_kernel<<<NSPLIT*BB*(NN/MQ), 128, SMEM_TOTAL>>>();
    reduce_kernel<<<BB*(NN/64), 256>>>(out);
}

// round 14
// speedup vs baseline: 1.5209x; 1.5015x over previous
#include <cuda_runtime.h>
#include <cuda_bf16.h>
#include <cuda_fp16.h>
#include <stdint.h>

#define BB 4
#define CC 64
#define WDIM 64
#define NN 4096
#define MQ 64
#define KTILE 32
#define NSPLIT 2
#define TILES_PER_SPLIT (NN/KTILE/NSPLIT)   // 64
#define L2E 1.44269504088896f
#define PBLK 32

#define QSTRIDE 80
#define KSTRIDE 80
#define VSTRIDE 144
// triple-buffered K/V (single fp16 V)
#define SM_Q   0                 // 64 x 80 = 5120
#define SM_K   5120              // 3 x 2560
#define KBUF   2560
#define SM_VH  12800             // 3 x 4608
#define VBUF   4608
#define SMEM_TOTAL 26624

// ---- global scratch ----
__device__ __align__(16) __nv_bfloat16 g_Q16[BB*NN*32];
__device__ __align__(16) __nv_bfloat16 g_K16[BB*NN*32];
__device__ __align__(16) __half g_V16[BB*NN*CC];
__device__ __align__(16) float g_Opart[NSPLIT][BB][NN][CC];   // 8MB partials
__device__ float g_Spart[NSPLIT][BB][NN];
__device__ float g_Mpart[NSPLIT][BB][NN];

// ---- helpers ----
__device__ __forceinline__ uint32_t s2u(const void* p) {
    uint32_t a;
    asm("{ .reg .u64 t; cvta.to.shared.u64 t, %1; cvt.u32.u64 %0, t; }" : "=r"(a) : "l"(p));
    return a;
}
__device__ __forceinline__ float ex2f(float x) {
    float r; asm("ex2.approx.f32 %0, %1;" : "=f"(r) : "f"(x)); return r;
}
// packs: lower 16 bits = lo arg, upper 16 = hi arg
__device__ __forceinline__ uint32_t cvt2bf(float hi, float lo) {
    uint32_t r; asm("cvt.rn.bf16x2.f32 %0, %1, %2;" : "=r"(r) : "f"(hi), "f"(lo)); return r;
}
__device__ __forceinline__ uint32_t cvt2h(float hi, float lo) {
    __half2 h = __floats2half2_rn(lo, hi);      // .x = lo -> lower 16 bits
    return *(uint32_t*)&h;
}
__device__ __forceinline__ void cpa16(uint32_t dst, const void* src) {
    asm volatile("cp.async.cg.shared.global [%0], [%1], 16;" :: "r"(dst), "l"(src));
}
__device__ __forceinline__ void ldsm4(uint32_t* r, uint32_t a) {
    asm volatile("ldmatrix.sync.aligned.m8n8.x4.shared.b16 {%0,%1,%2,%3}, [%4];"
        : "=r"(r[0]), "=r"(r[1]), "=r"(r[2]), "=r"(r[3]) : "r"(a));
}
__device__ __forceinline__ void ldsm4t(uint32_t* r, uint32_t a) {
    asm volatile("ldmatrix.sync.aligned.m8n8.x4.trans.shared.b16 {%0,%1,%2,%3}, [%4];"
        : "=r"(r[0]), "=r"(r[1]), "=r"(r[2]), "=r"(r[3]) : "r"(a));
}
__device__ __forceinline__ void mma16816(float* d, const uint32_t* a, const uint32_t* b) {
    asm volatile(
        "mma.sync.aligned.m16n8k16.row.col.f32.bf16.bf16.f32 "
        "{%0,%1,%2,%3}, {%4,%5,%6,%7}, {%8,%9}, {%0,%1,%2,%3};"
        : "+f"(d[0]), "+f"(d[1]), "+f"(d[2]), "+f"(d[3])
        : "r"(a[0]), "r"(a[1]), "r"(a[2]), "r"(a[3]), "r"(b[0]), "r"(b[1]));
}
__device__ __forceinline__ void mma16816h(float* d, const uint32_t* a, const uint32_t* b) {
    asm volatile(
        "mma.sync.aligned.m16n8k16.row.col.f32.f16.f16.f32 "
        "{%0,%1,%2,%3}, {%4,%5,%6,%7}, {%8,%9}, {%0,%1,%2,%3};"
        : "+f"(d[0]), "+f"(d[1]), "+f"(d[2]), "+f"(d[3])
        : "r"(a[0]), "r"(a[1]), "r"(a[2]), "r"(a[3]), "r"(b[0]), "r"(b[1]));
}

// ---------------------------------------------------------------------------
// Prep: 1x1 convs -> packed bf16 Q/K + fp16 V.
// 512 blocks x 320 threads: 32 pixels x 10 warp-groups
//   g0 = q (8ch) + Q pack, g1 = k (8ch) + K pack, g2..g9 = V 8ch each.
// Packed 32-dim score layout (per row):
//  Q: [0-7]=qh, [8]=qh0,[9]=qh1, [10-17]=qh, [18-25]=ql, [26]=ql0,[27]=ql1, [28-31]=0
//  K: [0-7]=kh, [8]=col,[9]=row, [10-17]=kl, [18-25]=kh, [26]=col,[27]=row, [28-31]=0
// ---------------------------------------------------------------------------
__global__ __launch_bounds__(320) void prep_kernel(
    const float* __restrict__ x,
    const float* __restrict__ Wq, const float* __restrict__ bq,
    const float* __restrict__ Wk, const float* __restrict__ bk,
    const float* __restrict__ Wv, const float* __restrict__ bv)
{
    __shared__ float xs[CC][PBLK];     // 8KB
    __shared__ float wv_s[CC][CC];     // 16KB
    __shared__ float wq_s[8][CC];
    __shared__ float wk_s[8][CC];
    __shared__ float bv_s[CC];
    __shared__ float bq_s[8], bk_s[8];

    const int b  = blockIdx.x >> 7;
    const int n0 = (blockIdx.x & 127) * PBLK;
    const int t  = threadIdx.x;

    for (int i = t; i < CC*PBLK; i += 320)
        xs[i >> 5][i & 31] = x[(b*CC + (i >> 5))*NN + n0 + (i & 31)];
    for (int i = t; i < CC*CC; i += 320) wv_s[i >> 6][i & 63] = Wv[i];
    for (int i = t; i < 8*CC;  i += 320) { wq_s[i >> 6][i & 63] = Wq[i]; wk_s[i >> 6][i & 63] = Wk[i]; }
    if (t < CC) bv_s[t] = bv[t];
    if (t < 8)  { bq_s[t] = bq[t]; bk_s[t] = bk[t]; }
    __syncthreads();

    const int g = t >> 5;        // warp id 0..9
    const int p = t & 31;
    const int n = n0 + p;

    if (g == 0) {
        // ---- q projection + Q pack ----
        float acc[8];
        #pragma unroll
        for (int d = 0; d < 8; d++) acc[d] = 0.f;
        for (int c = 0; c < CC; c++) {
            float xc = xs[c][p];
            #pragma unroll
            for (int d = 0; d < 8; d++) acc[d] = fmaf(wq_s[d][c], xc, acc[d]);
        }
        float qv[8];
        #pragma unroll
        for (int d = 0; d < 8; d++) qv[d] = acc[d] + bq_s[d];

        uint32_t u[16];
        float lo[8];
        #pragma unroll
        for (int i = 0; i < 4; i++) {
            uint32_t hh = cvt2bf(qv[2*i+1], qv[2*i]);
            u[i] = hh;
            lo[2*i]   = qv[2*i]   - __uint_as_float(hh << 16);
            lo[2*i+1] = qv[2*i+1] - __uint_as_float(hh & 0xFFFF0000u);
        }
        u[4] = u[0];
        u[5] = u[0]; u[6] = u[1]; u[7] = u[2]; u[8] = u[3];
        #pragma unroll
        for (int i = 0; i < 4; i++) u[9+i] = cvt2bf(lo[2*i+1], lo[2*i]);
        u[13] = u[9];
        u[14] = 0; u[15] = 0;
        uint4* dst = (uint4*)&g_Q16[(size_t)(b*NN + n)*32];
        dst[0] = make_uint4(u[0],u[1],u[2],u[3]);
        dst[1] = make_uint4(u[4],u[5],u[6],u[7]);
        dst[2] = make_uint4(u[8],u[9],u[10],u[11]);
        dst[3] = make_uint4(u[12],u[13],u[14],u[15]);
    } else if (g == 1) {
        // ---- k projection + K pack ----
        float acc[8];
        #pragma unroll
        for (int d = 0; d < 8; d++) acc[d] = 0.f;
        for (int c = 0; c < CC; c++) {
            float xc = xs[c][p];
            #pragma unroll
            for (int d = 0; d < 8; d++) acc[d] = fmaf(wk_s[d][c], xc, acc[d]);
        }
        float kv[8];
        #pragma unroll
        for (int d = 0; d < 8; d++) kv[d] = acc[d] + bk_s[d];

        uint32_t u[16];
        float lo[8];
        #pragma unroll
        for (int i = 0; i < 4; i++) {
            uint32_t hh = cvt2bf(kv[2*i+1], kv[2*i]);
            u[i] = hh;
            lo[2*i]   = kv[2*i]   - __uint_as_float(hh << 16);
            lo[2*i+1] = kv[2*i+1] - __uint_as_float(hh & 0xFFFF0000u);
        }
        float colc = (float)(n % WDIM) - 31.5f;   // exact in bf16
        float rowc = (float)(n / WDIM) - 31.5f;
        u[4] = cvt2bf(rowc, colc);
        #pragma unroll
        for (int i = 0; i < 4; i++) u[5+i] = cvt2bf(lo[2*i+1], lo[2*i]);
        u[9] = u[0]; u[10] = u[1]; u[11] = u[2]; u[12] = u[3];
        u[13] = u[4];
        u[14] = 0; u[15] = 0;
        uint4* dst = (uint4*)&g_K16[(size_t)(b*NN + n)*32];
        dst[0] = make_uint4(u[0],u[1],u[2],u[3]);
        dst[1] = make_uint4(u[4],u[5],u[6],u[7]);
        dst[2] = make_uint4(u[8],u[9],u[10],u[11]);
        dst[3] = make_uint4(u[12],u[13],u[14],u[15]);
    } else {
        // ---- V projection: 8 channels per warp-group, single fp16 ----
        const int e0 = (g - 2) * 8;
        float acc[8];
        #pragma unroll
        for (int e = 0; e < 8; e++) acc[e] = 0.f;
        for (int c = 0; c < CC; c++) {
            float xc = xs[c][p];
            #pragma unroll
            for (int e = 0; e < 8; e++) acc[e] = fmaf(wv_s[e0 + e][c], xc, acc[e]);
        }
        const size_t gbase = (size_t)(b*NN + n)*CC + e0;
        #pragma unroll
        for (int e = 0; e < 8; e++)
            g_V16[gbase + e] = __float2half(acc[e] + bv_s[e0 + e]);
    }
}

// ---------------------------------------------------------------------------
// Split-K mma.sync flash attention: 512 CTAs (2 splits x 4 b x 64 qtiles),
// 128 threads (4 warps x 16 query rows), 32-key tiles.
// Scores: packed 32-dim bf16 contraction (3-term hi/lo, validated).
// Softmax: per-row running max + per-tile rescale (classic flash) so P fits
// fp16 range. PV: SINGLE-term fp16. Partials merged across splits with max
// exchange. Triple-buffered K/V, one __syncthreads per tile.
// ---------------------------------------------------------------------------
#define STAGE(tile, bbuf) do {                                              \
    int m0s = (tile)*KTILE;                                                 \
    { int row = t >> 2, seg = t & 3;                                        \
      cpa16(sb + SM_K + (bbuf)*KBUF + row*KSTRIDE + seg*16,                 \
            &g_K16[(size_t)(b*NN + m0s + row)*32 + seg*8]); }               \
    _Pragma("unroll")                                                       \
    for (int j5 = 0; j5 < 2; j5++) {                                        \
        int id = t + 128*j5; int row = id >> 3, seg = id & 7;               \
        cpa16(sb + SM_VH + (bbuf)*VBUF + row*VSTRIDE + seg*16,              \
              &g_V16[(size_t)(b*NN + m0s + row)*CC + seg*8]);               \
    }                                                                       \
} while (0)

__global__ __launch_bounds__(128, 4) void attn_kernel()
{
    extern __shared__ char smem[];
    const uint32_t sb = s2u(smem);
    const int t = threadIdx.x;
    const int w = t >> 5;
    const int l = t & 31;
    const int sp = blockIdx.x >> 8;
    const int b  = (blockIdx.x >> 6) & 3;
    const int n0 = (blockIdx.x & 63) * MQ;
    const int qr0 = w * 16;
    const int t0 = sp * TILES_PER_SPLIT;

    // stage Q (plain loads): 64 rows x 64B
    #pragma unroll
    for (int j = 0; j < 2; j++) {
        int id = t + 128*j;
        int row = id >> 2, seg = id & 3;
        uint4 v = *(const uint4*)&g_Q16[(size_t)(b*NN + n0 + row)*32 + seg*8];
        *(uint4*)(smem + SM_Q + row*QSTRIDE + seg*16) = v;
    }

    // prefetch first tile of this split into buffer 0
    STAGE(t0, 0);
    asm volatile("cp.async.commit_group;" ::: "memory");

    __syncthreads();   // Q staged

    uint32_t qA[4], qB[4];
    {
        uint32_t qa = sb + SM_Q + (qr0 + (l & 7) + ((l >> 3) & 1)*8)*QSTRIDE + (l >> 4)*16;
        ldsm4(qA, qa);
        ldsm4(qB, qa + 32);
    }

    float O[8][4];
    #pragma unroll
    for (int j = 0; j < 8; j++) { O[j][0]=0.f; O[j][1]=0.f; O[j][2]=0.f; O[j][3]=0.f; }
    float sumA = 0.f, sumB = 0.f;
    float MA = -1e30f, MB = -1e30f;    // running row max (raw score units)

    int cb = 0, nb = 1;   // current / next buffer (mod 3)
    for (int ti = 0; ti < TILES_PER_SPLIT; ti++) {
        if (ti + 1 < TILES_PER_SPLIT) STAGE(t0 + ti + 1, nb);
        asm volatile("cp.async.commit_group;" ::: "memory");
        asm volatile("cp.async.wait_group 1;" ::: "memory");
        __syncthreads();   // single barrier per tile (triple buffer makes WAR safe)

        // ---- scores: single packed 32-dim contraction ----
        const uint32_t kbase = sb + SM_K + cb*KBUF;
        float S[4][4];
        #pragma unroll
        for (int p2 = 0; p2 < 2; p2++) {
            uint32_t ka = kbase + (p2*16 + (l & 7) + (l >> 4)*8)*KSTRIDE + ((l >> 3) & 1)*16;
            uint32_t kA[4], kB[4];
            ldsm4(kA, ka);
            ldsm4(kB, ka + 32);
            float* s0 = S[2*p2]; float* s1 = S[2*p2+1];
            s0[0]=0.f; s0[1]=0.f; s0[2]=0.f; s0[3]=0.f;
            s1[0]=0.f; s1[1]=0.f; s1[2]=0.f; s1[3]=0.f;
            mma16816(s0, qA, kA);     mma16816(s0, qB, kB);
            mma16816(s1, qA, kA + 2); mma16816(s1, qB, kB + 2);
        }

        // ---- per-row tile max (rows live in lane groups of 4) ----
        float rmA = fmaxf(fmaxf(S[0][0], S[0][1]), fmaxf(S[1][0], S[1][1]));
        rmA = fmaxf(rmA, fmaxf(fmaxf(S[2][0], S[2][1]), fmaxf(S[3][0], S[3][1])));
        float rmB = fmaxf(fmaxf(S[0][2], S[0][3]), fmaxf(S[1][2], S[1][3]));
        rmB = fmaxf(rmB, fmaxf(fmaxf(S[2][2], S[2][3]), fmaxf(S[3][2], S[3][3])));
        rmA = fmaxf(rmA, __shfl_xor_sync(0xffffffffu, rmA, 1));
        rmA = fmaxf(rmA, __shfl_xor_sync(0xffffffffu, rmA, 2));
        rmB = fmaxf(rmB, __shfl_xor_sync(0xffffffffu, rmB, 1));
        rmB = fmaxf(rmB, __shfl_xor_sync(0xffffffffu, rmB, 2));

        float newA = fmaxf(MA, rmA);
        float newB = fmaxf(MB, rmB);
        float alphaA = ex2f((MA - newA) * L2E);
        float alphaB = ex2f((MB - newB) * L2E);
        MA = newA; MB = newB;
        const float cA = newA * L2E;
        const float cB = newB * L2E;
        sumA *= alphaA; sumB *= alphaB;
        #pragma unroll
        for (int j = 0; j < 8; j++) {
            O[j][0] *= alphaA; O[j][1] *= alphaA;
            O[j][2] *= alphaB; O[j][3] *= alphaB;
        }

        // ---- exp (shifted by running row max) ----
        #pragma unroll
        for (int j = 0; j < 4; j++) {
            S[j][0] = ex2f(fmaf(S[j][0], L2E, -cA));
            S[j][1] = ex2f(fmaf(S[j][1], L2E, -cA));
            S[j][2] = ex2f(fmaf(S[j][2], L2E, -cB));
            S[j][3] = ex2f(fmaf(S[j][3], L2E, -cB));
            sumA += S[j][0] + S[j][1];
            sumB += S[j][2] + S[j][3];
        }

        // ---- PV: O += P(fp16) x V(fp16), single term ----
        const uint32_t vhb = sb + SM_VH + cb*VBUF;
        #pragma unroll
        for (int kt = 0; kt < 2; kt++) {
            const float* sa = S[2*kt];
            const float* sc = S[2*kt+1];
            uint32_t ph[4];
            ph[0] = cvt2h(sa[1], sa[0]);
            ph[1] = cvt2h(sa[3], sa[2]);
            ph[2] = cvt2h(sc[1], sc[0]);
            ph[3] = cvt2h(sc[3], sc[2]);
            uint32_t rowoff = (kt*16 + (l & 7) + ((l >> 3) & 1)*8)*VSTRIDE + (l >> 4)*16;
            #pragma unroll
            for (int cp = 0; cp < 4; cp++) {
                uint32_t vh[4];
                ldsm4t(vh, vhb + rowoff + cp*32);
                mma16816h(O[2*cp],     ph, vh);
                mma16816h(O[2*cp + 1], ph, vh + 2);
            }
        }

        cb = nb;
        nb = (nb == 2) ? 0 : nb + 1;
    }

    // ---- epilogue: write UNNORMALIZED partials + per-row (sum, max) ----
    sumA += __shfl_xor_sync(0xffffffffu, sumA, 1);
    sumA += __shfl_xor_sync(0xffffffffu, sumA, 2);
    sumB += __shfl_xor_sync(0xffffffffu, sumB, 1);
    sumB += __shfl_xor_sync(0xffffffffu, sumB, 2);

    const int nA = n0 + qr0 + (l >> 2);
    if ((l & 3) == 0) {
        g_Spart[sp][b][nA]     = sumA;
        g_Spart[sp][b][nA + 8] = sumB;
        g_Mpart[sp][b][nA]     = MA;
        g_Mpart[sp][b][nA + 8] = MB;
    }
    #pragma unroll
    for (int j = 0; j < 8; j++) {
        int ch = j*8 + (l & 3)*2;
        *(float2*)&g_Opart[sp][b][nA][ch]     = make_float2(O[j][0], O[j][1]);
        *(float2*)&g_Opart[sp][b][nA + 8][ch] = make_float2(O[j][2], O[j][3]);
    }
}

// ---------------------------------------------------------------------------
// Reduce with max exchange:
//   Mg = max(M0,M1); w_sp = 2^((M_sp-Mg)*L2E)
//   out[b][c][n] = (O0*w0 + O1*w1)[n][c] / (S0*w0 + S1*w1)[n]
// 256 blocks x 256 threads, coalesced via 64x64 smem transpose.
// ---------------------------------------------------------------------------
__global__ __launch_bounds__(256) void reduce_kernel(float* __restrict__ out)
{
    __shared__ float tile[CC][65];
    __shared__ float w0_s[64], w1_s[64], inv_s[64];
    const int b  = blockIdx.x >> 6;
    const int n0 = (blockIdx.x & 63) * 64;
    const int t  = threadIdx.x;

    if (t < 64) {
        float M0 = g_Mpart[0][b][n0 + t];
        float M1 = g_Mpart[1][b][n0 + t];
        float Mg = fmaxf(M0, M1);
        float w0 = ex2f((M0 - Mg) * L2E);
        float w1 = ex2f((M1 - Mg) * L2E);
        w0_s[t] = w0; w1_s[t] = w1;
        inv_s[t] = 1.0f / (g_Spart[0][b][n0 + t]*w0 + g_Spart[1][b][n0 + t]*w1);
    }
    __syncthreads();

    #pragma unroll
    for (int j = 0; j < 4; j++) {
        int idx = t + 256*j;
        int r = idx >> 4, c4 = (idx & 15)*4;
        float4 a0 = *(const float4*)&g_Opart[0][b][n0 + r][c4];
        float4 a1 = *(const float4*)&g_Opart[1][b][n0 + r][c4];
        float w0 = w0_s[r], w1 = w1_s[r], iv = inv_s[r];
        tile[c4    ][r] = (a0.x*w0 + a1.x*w1) * iv;
        tile[c4 + 1][r] = (a0.y*w0 + a1.y*w1) * iv;
        tile[c4 + 2][r] = (a0.z*w0 + a1.z*w1) * iv;
        tile[c4 + 3][r] = (a0.w*w0 + a1.w*w1) * iv;
    }
    __syncthreads();

    #pragma unroll
    for (int j = 0; j < 4; j++) {
        int idx = t + 256*j;
        int c = idx >> 4, nn = (idx & 15)*4;
        // scalar LDS (row stride 65 floats not 16B-aligned); vector STG
        float4 vv = make_float4(tile[c][nn], tile[c][nn + 1],
                                tile[c][nn + 2], tile[c][nn + 3]);
        *(float4*)&out[(size_t)(b*CC + c)*NN + n0 + nn] = vv;
    }
}

extern "C" void kernel_launch(void* const* d_in, const int* in_sizes, int n_in,
                              void* d_out, int out_size)
{
    const float* x  = (const float*)d_in[0];
    const float* Wq = (const float*)d_in[1];
    const float* bq = (const float*)d_in[2];
    const float* Wk = (const float*)d_in[3];
    const float* bk = (const float*)d_in[4];
    const float* Wv = (const float*)d_in[5];
    const float* bv = (const float*)d_in[6];
    float* out = (float*)d_out;

    prep_kernel<<<BB*(NN/PBLK), 320>>>(x, Wq, bq, Wk, bk, Wv, bv);
    attn_kernel<<<NSPLIT*BB*(NN/MQ), 128, SMEM_TOTAL>>>();
    reduce_kernel<<<BB*(NN/64), 256>>>(out);
}